// round 5
// baseline (speedup 1.0000x reference)
#include <cuda_runtime.h>
#include <math.h>

#define BB   512
#define TT   128
#define DIN  256
#define HH   1024
#define G4   4096          // 4*HH
#define MTOT (TT*BB)       // 65536

// ---------------- scratch (device globals: no allocations allowed) ----------
__device__ float g_X [(size_t)TT * BB * G4];   // 1 GiB: gate pre-activations, reused per layer
__device__ float g_H1[(size_t)TT * BB * HH];   // 256 MB: layer-1 hidden history
__device__ float g_H2[(size_t)TT * BB * HH];   // 256 MB: layer-2 hidden history
__device__ float g_c [BB * HH];                // cell state (reused per layer)
__device__ float g_zero[BB * HH];              // never written -> stays zero (h_{-1})

// ---------------- fp32x2 packed-FMA helpers (Blackwell) ---------------------
__device__ __forceinline__ unsigned long long dup2(float a) {
    unsigned long long r;
    asm("mov.b64 %0, {%1, %1};" : "=l"(r) : "r"(__float_as_uint(a)));
    return r;
}
__device__ __forceinline__ void ffma2(unsigned long long& d,
                                      unsigned long long a,
                                      unsigned long long b) {
    asm("fma.rn.f32x2 %0, %1, %2, %0;" : "+l"(d) : "l"(a), "l"(b));
}
__device__ __forceinline__ float lo2(unsigned long long v) { return __uint_as_float((unsigned)v); }
__device__ __forceinline__ float hi2(unsigned long long v) { return __uint_as_float((unsigned)(v >> 32)); }
__device__ __forceinline__ float sigmoidf_(float x) { return 1.f / (1.f + expf(-x)); }

// ============================================================================
// Big GEMM (UNCHANGED from R3 — measured ~106 TF/s, 78% of FFMA2 ceiling):
// g_X[m][n] = A[m][:] @ W[:, n] + bias[n]
// ============================================================================
template<int KD, bool CHARS>
__global__ __launch_bounds__(256, 2)
void gemm_bias_kernel(const float* __restrict__ A,
                      const float* __restrict__ W,
                      const float* __restrict__ bias)
{
    __shared__ __align__(16) float As[16][132];
    __shared__ __align__(16) float Bs[16][128];

    const int tid = threadIdx.x;
    const int tx  = tid & 15;
    const int ty  = tid >> 4;
    const int n0  = blockIdx.x * 128;
    const int m0  = blockIdx.y * 128;

    const float* Abase = CHARS ? A : g_H1;

    unsigned long long acc[8][4];
    #pragma unroll
    for (int i = 0; i < 8; i++)
        #pragma unroll
        for (int p = 0; p < 4; p++) acc[i][p] = 0ull;

    const int a_k = tid & 15;
    const int a_m = tid >> 4;
    const int b_c = tid & 127;
    const int b_k = tid >> 7;

    for (int kt = 0; kt < KD; kt += 16) {
        #pragma unroll
        for (int r = 0; r < 8; r++) {
            int m = m0 + a_m + 16 * r;
            size_t row = CHARS ? ((size_t)(m & 511) * TT + (m >> 9)) * KD
                               : (size_t)m * KD;
            As[a_k][a_m + 16 * r] = Abase[row + kt + a_k];
        }
        #pragma unroll
        for (int r = 0; r < 8; r++) {
            int k = b_k + 2 * r;
            Bs[k][b_c] = W[(size_t)(kt + k) * G4 + n0 + b_c];
        }
        __syncthreads();

        #pragma unroll
        for (int k = 0; k < 16; k++) {
            float4 a0 = *(const float4*)&As[k][ty * 4];
            float4 a1 = *(const float4*)&As[k][64 + ty * 4];
            unsigned long long bp[4];
            bp[0] = *(const unsigned long long*)&Bs[k][tx * 4];
            bp[1] = *(const unsigned long long*)&Bs[k][tx * 4 + 2];
            bp[2] = *(const unsigned long long*)&Bs[k][64 + tx * 4];
            bp[3] = *(const unsigned long long*)&Bs[k][64 + tx * 4 + 2];
            float av[8] = {a0.x, a0.y, a0.z, a0.w, a1.x, a1.y, a1.z, a1.w};
            #pragma unroll
            for (int i = 0; i < 8; i++) {
                unsigned long long ad = dup2(av[i]);
                #pragma unroll
                for (int p = 0; p < 4; p++) ffma2(acc[i][p], ad, bp[p]);
            }
        }
        __syncthreads();
    }

    #pragma unroll
    for (int i = 0; i < 8; i++) {
        int m = m0 + ((i < 4) ? (ty * 4 + i) : (64 + ty * 4 + i - 4));
        #pragma unroll
        for (int q = 0; q < 2; q++) {
            int n = n0 + q * 64 + tx * 4;
            float4 v;
            v.x = lo2(acc[i][q * 2])     + bias[n + 0];
            v.y = hi2(acc[i][q * 2])     + bias[n + 1];
            v.z = lo2(acc[i][q * 2 + 1]) + bias[n + 2];
            v.w = hi2(acc[i][q * 2 + 1]) + bias[n + 3];
            *(float4*)&g_X[(size_t)m * G4 + n] = v;
        }
    }
}

// ============================================================================
// Fused LSTM step v2: 64(batch) x 128(cols = 32 j x 4 gates) tile.
// grid = (HH/32, BB/64) = (32, 8) = 256 blocks -> 2 blocks/SM (16 warps/SM).
// Double-buffered smem + register prefetch: one __syncthreads per K-tile.
// ============================================================================
__global__ __launch_bounds__(256, 2)
void lstm_step_kernel(const float* __restrict__ U, int t, int layer)
{
    __shared__ __align__(16) float As[2][16][68];    // [buf][k][m]
    __shared__ __align__(16) float Bs[2][16][128];   // [buf][k][gate*32 + j]

    const int tid = threadIdx.x;
    const int tx  = tid & 15;
    const int ty  = tid >> 4;       // 0..15
    const int j0  = blockIdx.x * 32;
    const int m0  = blockIdx.y * 64;

    const float* Hbuf = layer ? g_H2 : g_H1;
    const float* h_in = (t == 0) ? g_zero : (Hbuf + (size_t)(t - 1) * BB * HH);
    float*       h_out = (float*)(Hbuf + (size_t)t * BB * HH);
    const float* X_t  = g_X + (size_t)t * BB * G4;

    unsigned long long acc[4][4];   // [m-sub][gate], packed pair over (j, j+1)
    #pragma unroll
    for (int i = 0; i < 4; i++)
        #pragma unroll
        for (int g = 0; g < 4; g++) acc[i][g] = 0ull;

    // global-load assignments
    const int a_k = tid & 15;       // k within tile
    const int a_m = tid >> 4;       // base m (0..15), rows a_m + 16*r, r<4
    const int b_c = tid & 127;      // packed col
    const int b_k = tid >> 7;       // 0..1, rows b_k + 2*r, r<8
    const int bg  = b_c >> 5;
    const int bj  = b_c & 31;

    const float* Ap0 = h_in + (size_t)(m0 + a_m +  0) * HH + a_k;
    const float* Ap1 = h_in + (size_t)(m0 + a_m + 16) * HH + a_k;
    const float* Ap2 = h_in + (size_t)(m0 + a_m + 32) * HH + a_k;
    const float* Ap3 = h_in + (size_t)(m0 + a_m + 48) * HH + a_k;
    const float* Bp  = U + (size_t)b_k * G4 + (size_t)bg * HH + j0 + bj;

    float rA[4], rB[8];

    // prefetch + store tile kt=0
    rA[0] = Ap0[0]; rA[1] = Ap1[0]; rA[2] = Ap2[0]; rA[3] = Ap3[0];
    #pragma unroll
    for (int r = 0; r < 8; r++) rB[r] = Bp[(size_t)(2 * r) * G4];
    #pragma unroll
    for (int r = 0; r < 4; r++) As[0][a_k][a_m + 16 * r] = rA[r];
    #pragma unroll
    for (int r = 0; r < 8; r++) Bs[0][b_k + 2 * r][b_c] = rB[r];
    __syncthreads();

    int buf = 0;
    for (int kt = 0; kt < HH; kt += 16) {
        const int nkt = kt + 16;
        if (nkt < HH) {
            rA[0] = Ap0[nkt]; rA[1] = Ap1[nkt]; rA[2] = Ap2[nkt]; rA[3] = Ap3[nkt];
            #pragma unroll
            for (int r = 0; r < 8; r++) rB[r] = Bp[(size_t)(nkt + 2 * r) * G4];
        }

        #pragma unroll
        for (int k = 0; k < 16; k++) {
            float4 a0 = *(const float4*)&As[buf][k][ty * 4];
            unsigned long long bp[4];
            #pragma unroll
            for (int g = 0; g < 4; g++)
                bp[g] = *(const unsigned long long*)&Bs[buf][k][g * 32 + tx * 2];
            float av[4] = {a0.x, a0.y, a0.z, a0.w};
            #pragma unroll
            for (int i = 0; i < 4; i++) {
                unsigned long long ad = dup2(av[i]);
                #pragma unroll
                for (int g = 0; g < 4; g++) ffma2(acc[i][g], ad, bp[g]);
            }
        }

        if (nkt < HH) {
            #pragma unroll
            for (int r = 0; r < 4; r++) As[buf ^ 1][a_k][a_m + 16 * r] = rA[r];
            #pragma unroll
            for (int r = 0; r < 8; r++) Bs[buf ^ 1][b_k + 2 * r][b_c] = rB[r];
        }
        __syncthreads();
        buf ^= 1;
    }

    // Epilogue: gates + state update. c is thread-exclusive; h_out != h_in.
    #pragma unroll
    for (int i = 0; i < 4; i++) {
        int m = m0 + ty * 4 + i;
        const float* Xrow = X_t + (size_t)m * G4;
        #pragma unroll
        for (int jj = 0; jj < 2; jj++) {
            int j = j0 + tx * 2 + jj;
            float zi = (jj ? hi2(acc[i][0]) : lo2(acc[i][0])) + Xrow[j];
            float zf = (jj ? hi2(acc[i][1]) : lo2(acc[i][1])) + Xrow[HH + j];
            float zg = (jj ? hi2(acc[i][2]) : lo2(acc[i][2])) + Xrow[2 * HH + j];
            float zo = (jj ? hi2(acc[i][3]) : lo2(acc[i][3])) + Xrow[3 * HH + j];
            float ig = sigmoidf_(zi);
            float fg = sigmoidf_(zf);
            float gg = tanhf(zg);
            float og = sigmoidf_(zo);
            size_t cidx = (size_t)m * HH + j;
            float c = fg * g_c[cidx] + ig * gg;
            g_c[cidx]   = c;
            h_out[cidx] = og * tanhf(c);
        }
    }
}

// ---------------- small kernels ---------------------------------------------
__global__ void zero_c_kernel()
{
    int i = blockIdx.x * blockDim.x + threadIdx.x;
    if (i < BB * HH) g_c[i] = 0.f;
}

__global__ void dense_out_kernel(const int* __restrict__ seq,
                                 const float* __restrict__ Wd,
                                 const float* __restrict__ bd,
                                 float* __restrict__ out)
{
    int b   = blockIdx.x;
    int tid = threadIdx.x;   // 128 threads
    const float* hrow = g_H2 + ((size_t)(seq[b] - 1) * BB + b) * HH;
    float s0 = 0.f, s1 = 0.f, s2 = 0.f;
    for (int j = tid; j < HH; j += 128) {
        float h = hrow[j];
        s0 += h * Wd[j * 3 + 0];
        s1 += h * Wd[j * 3 + 1];
        s2 += h * Wd[j * 3 + 2];
    }
    __shared__ float sm[3][128];
    sm[0][tid] = s0; sm[1][tid] = s1; sm[2][tid] = s2;
    __syncthreads();
    for (int s = 64; s > 0; s >>= 1) {
        if (tid < s) {
            sm[0][tid] += sm[0][tid + s];
            sm[1][tid] += sm[1][tid + s];
            sm[2][tid] += sm[2][tid + s];
        }
        __syncthreads();
    }
    if (tid == 0) {
        out[b * 3 + 0] = fmaxf(sm[0][0] + bd[0], 0.f);
        out[b * 3 + 1] = fmaxf(sm[1][0] + bd[1], 0.f);
        out[b * 3 + 2] = fmaxf(sm[2][0] + bd[2], 0.f);
    }
}

// ---------------- launch -----------------------------------------------------
extern "C" void kernel_launch(void* const* d_in, const int* in_sizes, int n_in,
                              void* d_out, int out_size)
{
    const float* chars = (const float*)d_in[0];
    const int*   seq   = (const int*)  d_in[1];
    const float* W1    = (const float*)d_in[2];
    const float* U1    = (const float*)d_in[3];
    const float* b1    = (const float*)d_in[4];
    const float* W2    = (const float*)d_in[5];
    const float* U2    = (const float*)d_in[6];
    const float* b2    = (const float*)d_in[7];
    const float* Wd    = (const float*)d_in[8];
    const float* bd    = (const float*)d_in[9];
    float*       out   = (float*)d_out;

    dim3 blk(256);
    dim3 gX(G4 / 128, MTOT / 128);   // 32 x 512
    dim3 gS(HH / 32, BB / 64);       // 32 x 8 = 256 blocks

    // Layer 1: X = chars@W1 + b1 (all timesteps), then 128 recurrent steps
    gemm_bias_kernel<DIN, true><<<gX, blk>>>(chars, W1, b1);
    zero_c_kernel<<<(BB * HH + 255) / 256, 256>>>();
    for (int t = 0; t < TT; t++)
        lstm_step_kernel<<<gS, blk>>>(U1, t, 0);

    // Layer 2: X = H1@W2 + b2 (reuses g_X), then 128 recurrent steps
    gemm_bias_kernel<HH, false><<<gX, blk>>>(nullptr, W2, b2);
    zero_c_kernel<<<(BB * HH + 255) / 256, 256>>>();
    for (int t = 0; t < TT; t++)
        lstm_step_kernel<<<gS, blk>>>(U2, t, 1);

    // Gather last valid h2 + dense + relu
    dense_out_kernel<<<BB, 128>>>(seq, Wd, bd, out);
}

// round 7
// speedup vs baseline: 1.7651x; 1.7651x over previous
#include <cuda_runtime.h>
#include <cuda_bf16.h>
#include <math.h>
#include <stdint.h>

#define BB   512
#define TT   128
#define DIN  256
#define HH   1024
#define G4   4096          // 4*HH
#define MTOT (TT*BB)       // 65536
#define NCH  16            // K chunks per step (1024/64)
#define CK   64            // k per chunk (64 bf16 = 128B rows)

// ---------------- scratch (device globals: no allocations allowed) ----------
__device__ float g_X [(size_t)TT * BB * G4];   // gate pre-activations (cols reordered n=j*4+g)
__device__ float g_H1[(size_t)TT * BB * HH];   // layer-1 fp32 hidden history
__device__ float g_H2[(size_t)TT * BB * HH];   // layer-2 fp32 hidden history
__device__ float g_c [BB * HH];                // cell state (reused per layer)

__device__ float g_Wr1[(size_t)DIN * G4];      // W1 cols reordered n=j*4+g
__device__ float g_Wr2[(size_t)HH  * G4];
__device__ float g_br1[G4];
__device__ float g_br2[G4];

// U transposed+gate-interleaved+bf16-split: [layer][n=j*4+g][k]
__device__ __nv_bfloat16 g_Uhi[2][(size_t)G4 * HH];
__device__ __nv_bfloat16 g_Ulo[2][(size_t)G4 * HH];
// h ping-pong, bf16 hi/lo split: [parity][m*HH + j]
__device__ __nv_bfloat16 g_hhi[2][(size_t)BB * HH];
__device__ __nv_bfloat16 g_hlo[2][(size_t)BB * HH];

// ---------------- helpers ----------------------------------------------------
__device__ __forceinline__ uint32_t smem_to_u32(const void* p) {
    uint32_t a;
    asm("{ .reg .u64 t; cvta.to.shared.u64 t, %1; cvt.u32.u64 %0, t; }"
        : "=r"(a) : "l"(p));
    return a;
}
#define SMEM_SWIZZLE_128B(b) ((b) ^ (((b) >> 3) & 0x70))

__device__ __forceinline__ void cp16(uint32_t dst, const void* src) {
    asm volatile("cp.async.cg.shared.global [%0], [%1], 16;" :: "r"(dst), "l"(src));
}
#define CP_COMMIT() asm volatile("cp.async.commit_group;" ::: "memory")
#define CP_WAIT(n)  asm volatile("cp.async.wait_group %0;" :: "n"(n) : "memory")

__device__ __forceinline__ void ldsm4(uint32_t* r, uint32_t addr) {
    asm volatile("ldmatrix.sync.aligned.m8n8.x4.shared.b16 {%0,%1,%2,%3}, [%4];"
        : "=r"(r[0]), "=r"(r[1]), "=r"(r[2]), "=r"(r[3]) : "r"(addr));
}
__device__ __forceinline__ void mma16816(float* d, const uint32_t* a, const uint32_t* b) {
    asm volatile("mma.sync.aligned.m16n8k16.row.col.f32.bf16.bf16.f32 "
        "{%0,%1,%2,%3}, {%4,%5,%6,%7}, {%8,%9}, {%0,%1,%2,%3};"
        : "+f"(d[0]), "+f"(d[1]), "+f"(d[2]), "+f"(d[3])
        : "r"(a[0]), "r"(a[1]), "r"(a[2]), "r"(a[3]), "r"(b[0]), "r"(b[1]));
}

__device__ __forceinline__ float sigmoidf_(float x) { return 1.f / (1.f + expf(-x)); }

// ---------------- fp32x2 packed-FMA helpers (input GEMM path) ----------------
__device__ __forceinline__ unsigned long long dup2(float a) {
    unsigned long long r;
    asm("mov.b64 %0, {%1, %1};" : "=l"(r) : "r"(__float_as_uint(a)));
    return r;
}
__device__ __forceinline__ void ffma2(unsigned long long& d, unsigned long long a,
                                      unsigned long long b) {
    asm("fma.rn.f32x2 %0, %1, %2, %0;" : "+l"(d) : "l"(a), "l"(b));
}
__device__ __forceinline__ float lo2(unsigned long long v) { return __uint_as_float((unsigned)v); }
__device__ __forceinline__ float hi2(unsigned long long v) { return __uint_as_float((unsigned)(v >> 32)); }

// ============================================================================
// Prep kernels
// ============================================================================
__global__ void reorder_W_kernel(const float* __restrict__ W,
                                 const float* __restrict__ b,
                                 int KD, int sel)
{
    float* Wr = sel ? g_Wr2 : g_Wr1;
    float* br = sel ? g_br2 : g_br1;
    int i = blockIdx.x * blockDim.x + threadIdx.x;
    if (i < KD * G4) {
        int k = i >> 12, n = i & 4095;
        int j = n >> 2, g = n & 3;
        Wr[i] = W[(size_t)k * G4 + g * HH + j];
    }
    if (i < G4) {
        int j = i >> 2, g = i & 3;
        br[i] = b[g * HH + j];
    }
}

__global__ void split_U_kernel(const float* __restrict__ U, int layer)
{
    int i = blockIdx.x * blockDim.x + threadIdx.x;   // i = n*HH + k
    if (i >= G4 * HH) return;
    int n = i >> 10, k = i & 1023;
    int j = n >> 2, g = n & 3;
    float v = U[(size_t)k * G4 + g * HH + j];
    __nv_bfloat16 hi = __float2bfloat16(v);
    __nv_bfloat16 lo = __float2bfloat16(v - __bfloat162float(hi));
    g_Uhi[layer][i] = hi;
    g_Ulo[layer][i] = lo;
}

__global__ void zero_state_kernel()
{
    int i = blockIdx.x * blockDim.x + threadIdx.x;
    if (i < BB * HH) {
        g_c[i] = 0.f;
        g_hhi[0][i] = __float2bfloat16(0.f);
        g_hlo[0][i] = __float2bfloat16(0.f);
    }
}

// ============================================================================
// Input-path GEMM (FFMA2, proven): g_X[m][n] = A[m][:] @ Wr[:, n] + br[n]
// ============================================================================
template<int KD, bool CHARS>
__global__ __launch_bounds__(256, 2)
void gemm_bias_kernel(const float* __restrict__ A)
{
    const float* __restrict__ W    = CHARS ? g_Wr1 : g_Wr2;
    const float* __restrict__ bias = CHARS ? g_br1 : g_br2;

    __shared__ __align__(16) float As[16][132];
    __shared__ __align__(16) float Bs[16][128];

    const int tid = threadIdx.x;
    const int tx  = tid & 15;
    const int ty  = tid >> 4;
    const int n0  = blockIdx.x * 128;
    const int m0  = blockIdx.y * 128;

    const float* Abase = CHARS ? A : g_H1;

    unsigned long long acc[8][4];
    #pragma unroll
    for (int i = 0; i < 8; i++)
        #pragma unroll
        for (int p = 0; p < 4; p++) acc[i][p] = 0ull;

    const int a_k = tid & 15;
    const int a_m = tid >> 4;
    const int b_c = tid & 127;
    const int b_k = tid >> 7;

    for (int kt = 0; kt < KD; kt += 16) {
        #pragma unroll
        for (int r = 0; r < 8; r++) {
            int m = m0 + a_m + 16 * r;
            size_t row = CHARS ? ((size_t)(m & 511) * TT + (m >> 9)) * KD
                               : (size_t)m * KD;
            As[a_k][a_m + 16 * r] = Abase[row + kt + a_k];
        }
        #pragma unroll
        for (int r = 0; r < 8; r++) {
            int k = b_k + 2 * r;
            Bs[k][b_c] = W[(size_t)(kt + k) * G4 + n0 + b_c];
        }
        __syncthreads();

        #pragma unroll
        for (int k = 0; k < 16; k++) {
            float4 a0 = *(const float4*)&As[k][ty * 4];
            float4 a1 = *(const float4*)&As[k][64 + ty * 4];
            unsigned long long bp[4];
            bp[0] = *(const unsigned long long*)&Bs[k][tx * 4];
            bp[1] = *(const unsigned long long*)&Bs[k][tx * 4 + 2];
            bp[2] = *(const unsigned long long*)&Bs[k][64 + tx * 4];
            bp[3] = *(const unsigned long long*)&Bs[k][64 + tx * 4 + 2];
            float av[8] = {a0.x, a0.y, a0.z, a0.w, a1.x, a1.y, a1.z, a1.w};
            #pragma unroll
            for (int i = 0; i < 8; i++) {
                unsigned long long ad = dup2(av[i]);
                #pragma unroll
                for (int p = 0; p < 4; p++) ffma2(acc[i][p], ad, bp[p]);
            }
        }
        __syncthreads();
    }

    #pragma unroll
    for (int i = 0; i < 8; i++) {
        int m = m0 + ((i < 4) ? (ty * 4 + i) : (64 + ty * 4 + i - 4));
        #pragma unroll
        for (int q = 0; q < 2; q++) {
            int n = n0 + q * 64 + tx * 4;
            float4 v;
            v.x = lo2(acc[i][q * 2])     + bias[n + 0];
            v.y = hi2(acc[i][q * 2])     + bias[n + 1];
            v.z = lo2(acc[i][q * 2 + 1]) + bias[n + 2];
            v.w = hi2(acc[i][q * 2 + 1]) + bias[n + 3];
            *(float4*)&g_X[(size_t)m * G4 + n] = v;
        }
    }
}

// ============================================================================
// Recurrent step via legacy tensor-core mma.sync (bf16, 3-term split, fp32 acc)
// Block: M=64(batch) x N=128(=32j x 4gates), K=1024. grid (32,8)=256 blocks.
// 8 warps, warp tile 32x32. cp.async double-buffered SW128 smem tiles.
// SMEM map (96KB): A[buf][hi/lo] 4x8KB @0; B[buf][hi/lo] 4x16KB @32KB.
// ============================================================================
#define SM_STEP_TOTAL 98304

__device__ __forceinline__ void issue_chunk(
    uint32_t sb, int buf, int kt,
    const __nv_bfloat16* hhi, const __nv_bfloat16* hlo,
    const __nv_bfloat16* Uhi, const __nv_bfloat16* Ulo,
    int m0, int nrow0, int tid)
{
    uint32_t aHi = sb + buf * 16384;
    uint32_t aLo = aHi + 8192;
    uint32_t bHi = sb + 32768 + buf * 32768;
    uint32_t bLo = bHi + 16384;
    #pragma unroll
    for (int i = 0; i < 2; i++) {                 // A: 64 rows x 8 segs
        int idx = tid + 256 * i;
        int row = idx >> 3, cs = idx & 7;
        uint32_t off = SMEM_SWIZZLE_128B((uint32_t)(row * 128 + cs * 16));
        size_t src = (size_t)(m0 + row) * HH + kt + cs * 8;
        cp16(aHi + off, hhi + src);
        cp16(aLo + off, hlo + src);
    }
    #pragma unroll
    for (int i = 0; i < 4; i++) {                 // B: 128 rows x 8 segs
        int idx = tid + 256 * i;
        int row = idx >> 3, cs = idx & 7;
        uint32_t off = SMEM_SWIZZLE_128B((uint32_t)(row * 128 + cs * 16));
        size_t src = (size_t)(nrow0 + row) * HH + kt + cs * 8;
        cp16(bHi + off, Uhi + src);
        cp16(bLo + off, Ulo + src);
    }
    CP_COMMIT();
}

__global__ __launch_bounds__(256, 2)
void lstm_step_mma(int t, int layer)
{
    extern __shared__ __align__(128) char smem[];
    const uint32_t sb = smem_to_u32(smem);
    const int tid  = threadIdx.x;
    const int wid  = tid >> 5;
    const int lane = tid & 31;
    const int nrow0 = blockIdx.x * 128;   // n-rows of U covered by this block
    const int m0    = blockIdx.y * 64;
    const int par   = t & 1;

    const __nv_bfloat16* hhi = g_hhi[par];
    const __nv_bfloat16* hlo = g_hlo[par];
    const __nv_bfloat16* Uhi = g_Uhi[layer];
    const __nv_bfloat16* Ulo = g_Ulo[layer];

    const int m_warp = (wid & 1) * 32;    // 2 m-tiles of 32
    const int n_warp = (wid >> 1) * 32;   // 4 n-tiles of 32

    float acc[2][4][4];
    #pragma unroll
    for (int mf = 0; mf < 2; mf++)
        #pragma unroll
        for (int nf = 0; nf < 4; nf++)
            #pragma unroll
            for (int d = 0; d < 4; d++) acc[mf][nf][d] = 0.f;

    const int rsel = lane & 15;
    const int csel = (lane >> 4) * 16;

    issue_chunk(sb, 0, 0, hhi, hlo, Uhi, Ulo, m0, nrow0, tid);

    int buf = 0;
    for (int c = 0; c < NCH; c++) {
        if (c + 1 < NCH) {
            issue_chunk(sb, buf ^ 1, (c + 1) * CK, hhi, hlo, Uhi, Ulo, m0, nrow0, tid);
            CP_WAIT(1);
        } else {
            CP_WAIT(0);
        }
        __syncthreads();

        const uint32_t sAh = sb + buf * 16384;
        const uint32_t sAl = sAh + 8192;
        const uint32_t sBh = sb + 32768 + buf * 32768;
        const uint32_t sBl = sBh + 16384;

        #pragma unroll
        for (int s = 0; s < 4; s++) {
            uint32_t aH[2][4], aL[2][4], bH[4][2], bL[4][2];
            #pragma unroll
            for (int mf = 0; mf < 2; mf++) {
                uint32_t off = SMEM_SWIZZLE_128B(
                    (uint32_t)((m_warp + mf * 16 + rsel) * 128 + s * 32 + csel));
                ldsm4(aH[mf], sAh + off);
                ldsm4(aL[mf], sAl + off);
            }
            #pragma unroll
            for (int nb = 0; nb < 2; nb++) {
                uint32_t off = SMEM_SWIZZLE_128B(
                    (uint32_t)((n_warp + nb * 16 + rsel) * 128 + s * 32 + csel));
                uint32_t r[4];
                ldsm4(r, sBh + off);
                bH[nb * 2][0] = r[0]; bH[nb * 2][1] = r[2];
                bH[nb * 2 + 1][0] = r[1]; bH[nb * 2 + 1][1] = r[3];
                ldsm4(r, sBl + off);
                bL[nb * 2][0] = r[0]; bL[nb * 2][1] = r[2];
                bL[nb * 2 + 1][0] = r[1]; bL[nb * 2 + 1][1] = r[3];
            }
            #pragma unroll
            for (int mf = 0; mf < 2; mf++)
                #pragma unroll
                for (int nf = 0; nf < 4; nf++) {
                    mma16816(acc[mf][nf], aH[mf], bH[nf]);
                    mma16816(acc[mf][nf], aH[mf], bL[nf]);
                    mma16816(acc[mf][nf], aL[mf], bH[nf]);
                }
        }
        __syncthreads();
        buf ^= 1;
    }

    // ---- epilogue: stage z via smem so each thread gets 4 gates of one j ----
    float* zs = (float*)smem;               // [64][132] fp32, 33.8KB (reuses tiles)
    #pragma unroll
    for (int mf = 0; mf < 2; mf++)
        #pragma unroll
        for (int nf = 0; nf < 4; nf++)
            #pragma unroll
            for (int d = 0; d < 4; d++) {
                int m = m_warp + mf * 16 + (lane >> 2) + (d >> 1) * 8;
                int n = n_warp + nf * 8 + (lane & 3) * 2 + (d & 1);
                zs[m * 132 + n] = acc[mf][nf][d];
            }
    __syncthreads();

    float* Hist = layer ? g_H2 : g_H1;
    __nv_bfloat16* nhhi = g_hhi[par ^ 1];
    __nv_bfloat16* nhlo = g_hlo[par ^ 1];
    const int j0 = blockIdx.x * 32;

    #pragma unroll
    for (int r = 0; r < 8; r++) {
        int e  = tid + 256 * r;
        int m  = e >> 5;
        int jl = e & 31;
        int mg = m0 + m;
        int j  = j0 + jl;
        float4 z = *(const float4*)&zs[m * 132 + jl * 4];
        const float* Xrow = g_X + ((size_t)t * BB + mg) * G4 + blockIdx.x * 128;
        float4 xz = *(const float4*)(Xrow + jl * 4);
        float zi = z.x + xz.x;
        float zf = z.y + xz.y;
        float zg = z.z + xz.z;
        float zo = z.w + xz.w;
        float ig = sigmoidf_(zi);
        float fg = sigmoidf_(zf);
        float gg = tanhf(zg);
        float og = sigmoidf_(zo);
        size_t cidx = (size_t)mg * HH + j;
        float cc = fg * g_c[cidx] + ig * gg;
        g_c[cidx] = cc;
        float h = og * tanhf(cc);
        Hist[((size_t)t * BB + mg) * HH + j] = h;
        __nv_bfloat16 hh = __float2bfloat16(h);
        nhhi[cidx] = hh;
        nhlo[cidx] = __float2bfloat16(h - __bfloat162float(hh));
    }
}

// ---------------- output head ------------------------------------------------
__global__ void dense_out_kernel(const int* __restrict__ seq,
                                 const float* __restrict__ Wd,
                                 const float* __restrict__ bd,
                                 float* __restrict__ out)
{
    int b   = blockIdx.x;
    int tid = threadIdx.x;   // 128 threads
    const float* hrow = g_H2 + ((size_t)(seq[b] - 1) * BB + b) * HH;
    float s0 = 0.f, s1 = 0.f, s2 = 0.f;
    for (int j = tid; j < HH; j += 128) {
        float h = hrow[j];
        s0 += h * Wd[j * 3 + 0];
        s1 += h * Wd[j * 3 + 1];
        s2 += h * Wd[j * 3 + 2];
    }
    __shared__ float sm[3][128];
    sm[0][tid] = s0; sm[1][tid] = s1; sm[2][tid] = s2;
    __syncthreads();
    for (int s = 64; s > 0; s >>= 1) {
        if (tid < s) {
            sm[0][tid] += sm[0][tid + s];
            sm[1][tid] += sm[1][tid + s];
            sm[2][tid] += sm[2][tid + s];
        }
        __syncthreads();
    }
    if (tid == 0) {
        out[b * 3 + 0] = fmaxf(sm[0][0] + bd[0], 0.f);
        out[b * 3 + 1] = fmaxf(sm[1][0] + bd[1], 0.f);
        out[b * 3 + 2] = fmaxf(sm[2][0] + bd[2], 0.f);
    }
}

// ---------------- launch -----------------------------------------------------
extern "C" void kernel_launch(void* const* d_in, const int* in_sizes, int n_in,
                              void* d_out, int out_size)
{
    const float* chars = (const float*)d_in[0];
    const int*   seq   = (const int*)  d_in[1];
    const float* W1    = (const float*)d_in[2];
    const float* U1    = (const float*)d_in[3];
    const float* b1    = (const float*)d_in[4];
    const float* W2    = (const float*)d_in[5];
    const float* U2    = (const float*)d_in[6];
    const float* b2    = (const float*)d_in[7];
    const float* Wd    = (const float*)d_in[8];
    const float* bd    = (const float*)d_in[9];
    float*       out   = (float*)d_out;

    cudaFuncSetAttribute(lstm_step_mma, cudaFuncAttributeMaxDynamicSharedMemorySize,
                         SM_STEP_TOTAL);

    dim3 blk(256);
    dim3 gX(G4 / 128, MTOT / 128);   // 32 x 512
    dim3 gS(G4 / 128, BB / 64);      // 32 x 8 = 256 blocks

    // --- prep (inside the graph; cheap) ---
    reorder_W_kernel<<<(DIN * G4 + 255) / 256, 256>>>(W1, b1, DIN, 0);
    reorder_W_kernel<<<(HH  * G4 + 255) / 256, 256>>>(W2, b2, HH,  1);
    split_U_kernel<<<(G4 * HH + 255) / 256, 256>>>(U1, 0);
    split_U_kernel<<<(G4 * HH + 255) / 256, 256>>>(U2, 1);

    // --- layer 1 ---
    gemm_bias_kernel<DIN, true><<<gX, blk>>>(chars);
    zero_state_kernel<<<(BB * HH + 255) / 256, 256>>>();
    for (int t = 0; t < TT; t++)
        lstm_step_mma<<<gS, blk, SM_STEP_TOTAL>>>(t, 0);

    // --- layer 2 ---
    gemm_bias_kernel<HH, false><<<gX, blk>>>(nullptr);
    zero_state_kernel<<<(BB * HH + 255) / 256, 256>>>();
    for (int t = 0; t < TT; t++)
        lstm_step_mma<<<gS, blk, SM_STEP_TOTAL>>>(t, 1);

    // --- gather + dense + relu ---
    dense_out_kernel<<<BB, 128>>>(seq, Wd, bd, out);
}